// round 1
// baseline (speedup 1.0000x reference)
#include <cuda_runtime.h>
#include <cstdint>

// out[b,h,w,c] = (vector[0,c] >= -5) ? ip1[b,h,w,c] : ip2[b,h,w,c]
// B=32,H=64,W=64,C=128 -> 16,777,216 f32 elements = 4,194,304 float4s.
// C=128 floats = 32 float4 channel-groups; float4 index j -> group j & 31.

static constexpr int THREADS = 256;

__global__ __launch_bounds__(THREADS)
void random_pick_kernel(const float4* __restrict__ ip1,
                        const float4* __restrict__ ip2,
                        const float* __restrict__ vec,   // vector[0,:], 128 floats
                        float4* __restrict__ out,
                        int n4)
{
    int j = blockIdx.x * THREADS + threadIdx.x;
    if (j >= n4) return;

    int g = j & 31;  // channel group (4 channels per float4)
    // 512-byte region; hits L1 after first touch.
    float4 v = __ldg(reinterpret_cast<const float4*>(vec) + g);

    bool m0 = v.x >= -5.0f;
    bool m1 = v.y >= -5.0f;
    bool m2 = v.z >= -5.0f;
    bool m3 = v.w >= -5.0f;

    float4 r;
    if (m0 & m1 & m2 & m3) {
        // Fast path: read only ip1 (probability ~1 for N(0,1) vector).
        r = __ldg(ip1 + j);
    } else if (!(m0 | m1 | m2 | m3)) {
        r = __ldg(ip2 + j);
    } else {
        // Mixed group (astronomically rare): per-lane select.
        float4 a = __ldg(ip1 + j);
        float4 b = __ldg(ip2 + j);
        r.x = m0 ? a.x : b.x;
        r.y = m1 ? a.y : b.y;
        r.z = m2 ? a.z : b.z;
        r.w = m3 ? a.w : b.w;
    }
    out[j] = r;
}

extern "C" void kernel_launch(void* const* d_in, const int* in_sizes, int n_in,
                              void* d_out, int out_size)
{
    const float4* ip1 = reinterpret_cast<const float4*>(d_in[0]);
    const float4* ip2 = reinterpret_cast<const float4*>(d_in[1]);
    const float*  vec = reinterpret_cast<const float*>(d_in[2]);  // [32,128]; row 0 used
    float4* out = reinterpret_cast<float4*>(d_out);

    int n4 = out_size / 4;  // 4,194,304
    int blocks = (n4 + THREADS - 1) / THREADS;
    random_pick_kernel<<<blocks, THREADS>>>(ip1, ip2, vec, out, n4);
}

// round 2
// speedup vs baseline: 1.0890x; 1.0890x over previous
#include <cuda_runtime.h>
#include <cstdint>

// out[b,h,w,c] = (vector[0,c] >= -5) ? ip1[b,h,w,c] : ip2[b,h,w,c]
// 16,777,216 f32 = 4,194,304 float4. C=128 f32 = 32 float4 channel-groups.
// Thread's float4 indices stride by THREADS=256 (== 0 mod 32), so its
// channel group is fixed -> one mask evaluation, then a pure streamed copy
// from the selected source with 8-way MLP.

static constexpr int THREADS = 256;
static constexpr int VPT = 8;  // float4 per thread

__global__ __launch_bounds__(THREADS)
void random_pick_kernel(const float4* __restrict__ ip1,
                        const float4* __restrict__ ip2,
                        const float* __restrict__ vec,
                        float4* __restrict__ out,
                        int n4)
{
    int base = blockIdx.x * (THREADS * VPT) + threadIdx.x;
    if (base >= n4) return;

    int g = base & 31;  // constant across this thread's elements
    float4 v = __ldg(reinterpret_cast<const float4*>(vec) + g);

    bool m0 = v.x >= -5.0f;
    bool m1 = v.y >= -5.0f;
    bool m2 = v.z >= -5.0f;
    bool m3 = v.w >= -5.0f;
    bool all  =  (m0 & m1 & m2 & m3);
    bool none = !(m0 | m1 | m2 | m3);

    if (all | none) {
        // Hot path (probability ~1 for N(0,1) vector): single-source stream.
        const float4* __restrict__ src = all ? ip1 : ip2;
        float4 r[VPT];
        #pragma unroll
        for (int i = 0; i < VPT; i++) {
            int j = base + i * THREADS;
            if (j < n4) r[i] = __ldcs(src + j);   // evict-first: no reuse
        }
        #pragma unroll
        for (int i = 0; i < VPT; i++) {
            int j = base + i * THREADS;
            if (j < n4) __stcs(out + j, r[i]);    // streaming store
        }
    } else {
        // Mixed channel group (astronomically rare): per-lane select.
        #pragma unroll
        for (int i = 0; i < VPT; i++) {
            int j = base + i * THREADS;
            if (j < n4) {
                float4 a = __ldcs(ip1 + j);
                float4 b = __ldcs(ip2 + j);
                float4 r;
                r.x = m0 ? a.x : b.x;
                r.y = m1 ? a.y : b.y;
                r.z = m2 ? a.z : b.z;
                r.w = m3 ? a.w : b.w;
                __stcs(out + j, r);
            }
        }
    }
}

extern "C" void kernel_launch(void* const* d_in, const int* in_sizes, int n_in,
                              void* d_out, int out_size)
{
    const float4* ip1 = reinterpret_cast<const float4*>(d_in[0]);
    const float4* ip2 = reinterpret_cast<const float4*>(d_in[1]);
    const float*  vec = reinterpret_cast<const float*>(d_in[2]);  // row 0 used
    float4* out = reinterpret_cast<float4*>(d_out);

    int n4 = out_size / 4;  // 4,194,304
    int per_block = THREADS * VPT;
    int blocks = (n4 + per_block - 1) / per_block;  // 2048
    random_pick_kernel<<<blocks, THREADS>>>(ip1, ip2, vec, out, n4);
}

// round 3
// speedup vs baseline: 1.2215x; 1.1217x over previous
#include <cuda_runtime.h>
#include <cstdint>

// out[b,h,w,c] = (vector[0,c] >= -5) ? ip1[b,h,w,c] : ip2[b,h,w,c]
// 4,194,304 float4 elements. C=128 f32 = 32 float4 channel-groups; thread
// stride THREADS=256 == 0 (mod 32) -> channel group fixed per thread.
// Cache policy: loads __ldcg (L2 evict-normal: keep ip1 resident across graph
// replays; skip L1, it is flushed per launch), stores __stcs (evict-first:
// output is never re-read, don't pollute L2).

static constexpr int THREADS = 256;
static constexpr int VPT = 8;  // float4 per thread

__global__ __launch_bounds__(THREADS)
void random_pick_kernel(const float4* __restrict__ ip1,
                        const float4* __restrict__ ip2,
                        const float* __restrict__ vec,
                        float4* __restrict__ out,
                        int n4)
{
    int base = blockIdx.x * (THREADS * VPT) + threadIdx.x;
    if (base >= n4) return;

    int g = base & 31;  // constant across this thread's elements
    float4 v = __ldg(reinterpret_cast<const float4*>(vec) + g);

    bool m0 = v.x >= -5.0f;
    bool m1 = v.y >= -5.0f;
    bool m2 = v.z >= -5.0f;
    bool m3 = v.w >= -5.0f;
    bool all  =  (m0 & m1 & m2 & m3);
    bool none = !(m0 | m1 | m2 | m3);

    if (all | none) {
        // Hot path (probability ~1 for N(0,1) vector): single-source stream.
        const float4* __restrict__ src = all ? ip1 : ip2;
        float4 r[VPT];
        #pragma unroll
        for (int i = 0; i < VPT; i++) {
            int j = base + i * THREADS;
            if (j < n4) r[i] = __ldcg(src + j);   // L2-resident read
        }
        #pragma unroll
        for (int i = 0; i < VPT; i++) {
            int j = base + i * THREADS;
            if (j < n4) __stcs(out + j, r[i]);    // streaming store
        }
    } else {
        // Mixed channel group (astronomically rare): per-lane select.
        #pragma unroll
        for (int i = 0; i < VPT; i++) {
            int j = base + i * THREADS;
            if (j < n4) {
                float4 a = __ldcg(ip1 + j);
                float4 b = __ldcg(ip2 + j);
                float4 r;
                r.x = m0 ? a.x : b.x;
                r.y = m1 ? a.y : b.y;
                r.z = m2 ? a.z : b.z;
                r.w = m3 ? a.w : b.w;
                __stcs(out + j, r);
            }
        }
    }
}

extern "C" void kernel_launch(void* const* d_in, const int* in_sizes, int n_in,
                              void* d_out, int out_size)
{
    const float4* ip1 = reinterpret_cast<const float4*>(d_in[0]);
    const float4* ip2 = reinterpret_cast<const float4*>(d_in[1]);
    const float*  vec = reinterpret_cast<const float*>(d_in[2]);  // row 0 used
    float4* out = reinterpret_cast<float4*>(d_out);

    int n4 = out_size / 4;  // 4,194,304
    int per_block = THREADS * VPT;
    int blocks = (n4 + per_block - 1) / per_block;  // 2048
    random_pick_kernel<<<blocks, THREADS>>>(ip1, ip2, vec, out, n4);
}